// round 1
// baseline (speedup 1.0000x reference)
#include <cuda_runtime.h>

#define NPTS   100000
#define BATCH  4096
#define KSEL   10
#define TPB    256
#define RPB    16      // rays per block
#define SUBS   16      // threads per ray
#define TILE   1024    // points per shared tile

__global__ __launch_bounds__(TPB)
void gs_topk_kernel(const float* __restrict__ rays_o,
                    const float* __restrict__ rays_d,
                    const float* __restrict__ xyz,
                    const float* __restrict__ fdc,
                    const float* __restrict__ opac,
                    float* __restrict__ out)
{
    __shared__ float4 tile[TILE];                       // 16 KB
    __shared__ float  scx[RPB], scy[RPB], scz[RPB], sC[RPB];
    __shared__ float  md2[RPB * SUBS * KSEL];           // 10 KB
    __shared__ int    midx[RPB * SUBS * KSEL];          // 10 KB

    const int t       = threadIdx.x;
    const int rl      = t & (RPB - 1);   // ray within block
    const int sub     = t >> 4;          // scanner id within ray
    const int rayBase = blockIdx.x * RPB;

    // Ray centers + |c|^2
    if (t < RPB) {
        int r = rayBase + t;
        float cx = fmaf(3.0f, rays_d[r * 3 + 0], rays_o[r * 3 + 0]);
        float cy = fmaf(3.0f, rays_d[r * 3 + 1], rays_o[r * 3 + 1]);
        float cz = fmaf(3.0f, rays_d[r * 3 + 2], rays_o[r * 3 + 2]);
        scx[t] = cx; scy[t] = cy; scz[t] = cz;
        sC[t]  = cx * cx + cy * cy + cz * cz;
    }
    __syncthreads();

    const float cx = scx[rl], cy = scy[rl], cz = scz[rl], C = sC[rl];

    // Per-thread sorted (ascending) top-K of squared distances
    float best[KSEL];
    int   bidx[KSEL];
#pragma unroll
    for (int j = 0; j < KSEL; j++) { best[j] = 3.0e38f; bidx[j] = 0; }
    float thresh = 3.0e38f;   // = best[K-1] - C  (compare in "s = q - 2*dot" domain)

    for (int base = 0; base < NPTS; base += TILE) {
        int cnt = min(TILE, NPTS - base);
        __syncthreads();
        // Cooperative tile load: (x, y, z, |x|^2)
        for (int i = t; i < cnt; i += TPB) {
            float x = xyz[(base + i) * 3 + 0];
            float y = xyz[(base + i) * 3 + 1];
            float z = xyz[(base + i) * 3 + 2];
            tile[i] = make_float4(x, y, z, fmaf(x, x, fmaf(y, y, z * z)));
        }
        __syncthreads();

#pragma unroll 4
        for (int i = sub; i < cnt; i += SUBS) {
            float4 p  = tile[i];
            float dot = fmaf(cx, p.x, fmaf(cy, p.y, cz * p.z));
            float s   = fmaf(-2.0f, dot, p.w);           // q - 2*dot
            if (s < thresh) {
                float v = s + C;                          // full squared distance
                int   ii = base + i;
#pragma unroll
                for (int j = 0; j < KSEL; j++) {
                    if (v < best[j]) {
                        float tv = best[j]; int ti = bidx[j];
                        best[j] = v; bidx[j] = ii;
                        v = tv; ii = ti;
                    }
                }
                thresh = best[KSEL - 1] - C;
            }
        }
    }

    // Dump per-thread sorted lists to shared
    const int lbase = (rl * SUBS + sub) * KSEL;
#pragma unroll
    for (int j = 0; j < KSEL; j++) { md2[lbase + j] = best[j]; midx[lbase + j] = bidx[j]; }

    // Parallel pairwise merge: 16 lists -> 1 sorted top-K per ray
    for (int stride = SUBS / 2; stride >= 1; stride >>= 1) {
        __syncthreads();
        if (sub < stride) {
            int a = (rl * SUBS + sub) * KSEL;
            int b = (rl * SUBS + sub + stride) * KSEL;
            float ov[KSEL]; int oi[KSEL];
            int ia = 0, ib = 0;
#pragma unroll
            for (int k = 0; k < KSEL; k++) {
                float va = md2[a + ia], vb = md2[b + ib];
                if (va <= vb) { ov[k] = va; oi[k] = midx[a + ia]; ia++; }
                else          { ov[k] = vb; oi[k] = midx[b + ib]; ib++; }
            }
#pragma unroll
            for (int k = 0; k < KSEL; k++) { md2[a + k] = ov[k]; midx[a + k] = oi[k]; }
        }
    }
    __syncthreads();

    // Epilogue: one thread per ray
    if (t < RPB) {
        int a = (t * SUBS) * KSEL;
        float wsum = 0.f, r0 = 0.f, g0 = 0.f, b0 = 0.f;
#pragma unroll
        for (int k = 0; k < KSEL; k++) {
            float d2 = md2[a + k];
            int   ii = midx[a + k];
            float d  = sqrtf(fmaxf(d2, 0.0f));
            float op = 1.0f / (1.0f + expf(-opac[ii]));
            float w  = expf(-0.1f * d) * op;
            wsum += w;
            float c0 = 1.0f / (1.0f + expf(-fdc[ii * 3 + 0]));
            float c1 = 1.0f / (1.0f + expf(-fdc[ii * 3 + 1]));
            float c2 = 1.0f / (1.0f + expf(-fdc[ii * 3 + 2]));
            r0 = fmaf(w, c0, r0);
            g0 = fmaf(w, c1, g0);
            b0 = fmaf(w, c2, b0);
        }
        float inv = 1.0f / (wsum + 1e-8f);
        int ray = rayBase + t;
        out[ray * 3 + 0] = r0 * inv;
        out[ray * 3 + 1] = g0 * inv;
        out[ray * 3 + 2] = b0 * inv;
    }
}

extern "C" void kernel_launch(void* const* d_in, const int* in_sizes, int n_in,
                              void* d_out, int out_size)
{
    const float* rays_o = (const float*)d_in[0];
    const float* rays_d = (const float*)d_in[1];
    const float* xyz    = (const float*)d_in[2];
    const float* fdc    = (const float*)d_in[3];
    const float* opac   = (const float*)d_in[4];
    float* out = (float*)d_out;

    gs_topk_kernel<<<BATCH / RPB, TPB>>>(rays_o, rays_d, xyz, fdc, opac, out);
}